// round 5
// baseline (speedup 1.0000x reference)
#include <cuda_runtime.h>
#include <math.h>

// MultiHeadAttention with exact 1.5-entmax across heads, fused single-pass.
// C=64, T=2048, E=512, H=8, d=64. 131072 tokens. Output fp32 [tok][512].
//
// Per 16-token tile (one block, 256 threads):
//  Phase A: q/k/v projections as a 128x64 @ 64x64 GEMM x3, packed fp32x2 FMA.
//  Phase B: 8x8 scores per token + exact entmax15 (sort-based threshold).
//  Phase C: out = attn @ v, coalesced float4 stores.

#define NTHREADS 256
#define TB 16                    // tokens per block
#define INV_SQRT_E 0.04419417382415922f   // 1/sqrt(512)

// shared memory layout (in floats)
#define OFF_W  0                 // sW[p][d*66+e] = W_p[e][d], 3*64*66 = 12672
#define OFF_B  12672             // biases, 3*64 = 192
#define OFF_XQ 12864             // x tile [128 rows][stride 66] = 8448; reused as Q [128][stride 65]
#define OFF_K  21312             // K [128][stride 65] = 8320
#define OFF_V  29632             // V [128][stride 68] = 8704 (16B-aligned rows for float4)
#define OFF_A  38336             // attn [128][stride 9] = 1152
#define SMEM_FLOATS 39488
#define SMEM_BYTES (SMEM_FLOATS * 4)

typedef unsigned long long u64;

__device__ __forceinline__ void fma2(u64 &acc, u64 a, u64 b) {
    // packed fp32x2 FMA: acc.lo += a.lo*b.lo; acc.hi += a.hi*b.hi
    asm("fma.rn.f32x2 %0, %1, %2, %0;" : "+l"(acc) : "l"(a), "l"(b));
}
__device__ __forceinline__ u64 pack2(float lo, float hi) {
    u64 r; asm("mov.b64 %0, {%1, %2};" : "=l"(r) : "f"(lo), "f"(hi)); return r;
}
__device__ __forceinline__ void unpack2(u64 v, float &lo, float &hi) {
    asm("mov.b64 {%0, %1}, %2;" : "=f"(lo), "=f"(hi) : "l"(v));
}

__global__ __launch_bounds__(NTHREADS, 1)
void mha_entmax_kernel(const float* __restrict__ x,
                       const float* __restrict__ Wq, const float* __restrict__ bq,
                       const float* __restrict__ Wk, const float* __restrict__ bk,
                       const float* __restrict__ Wv, const float* __restrict__ bv,
                       float* __restrict__ out)
{
    extern __shared__ float sm[];
    float* sW  = sm + OFF_W;
    float* sB  = sm + OFF_B;
    float* sXQ = sm + OFF_XQ;   // x during phase A (stride 66), then Q (stride 65)
    float* sK  = sm + OFF_K;
    float* sV  = sm + OFF_V;
    float* sA  = sm + OFF_A;

    const int tid = threadIdx.x;
    const int blk = blockIdx.x;

    // ---- stage weights transposed: sW[p][d*66 + e] = W_p[e*64 + d] ----
    #pragma unroll 4
    for (int idx = tid; idx < 4096; idx += NTHREADS) {
        int e = idx >> 6, d = idx & 63;
        int so = d * 66 + e;
        sW[so]        = Wq[idx];
        sW[4224 + so] = Wk[idx];
        sW[8448 + so] = Wv[idx];
    }
    if (tid < 64) { sB[tid] = bq[tid]; sB[64 + tid] = bk[tid]; sB[128 + tid] = bv[tid]; }

    // ---- stage x tile: rows = token*8 + head, 64 d each, stride 66 ----
    const float* gx = x + (size_t)blk * (TB * 512);
    #pragma unroll
    for (int i = 0; i < 32; i++) {
        int idx = i * NTHREADS + tid;      // 0..8191, coalesced
        float v = gx[idx];
        int row = idx >> 6;                // t*8 + h
        int d   = idx & 63;
        sXQ[row * 66 + d] = v;
    }
    __syncthreads();

    // ================= Phase A: projections (fp32x2 GEMM) =================
    // thread -> 8 rows (rg = tid>>4), 4 consecutive e (eg = tid&15), all 3 proj
    const int rg = tid >> 4;
    const int eg = tid & 15;
    const int e0 = eg * 4;

    u64 aq[8][2], ak[8][2], av[8][2];
    {
        u64 bq01 = pack2(sB[e0],       sB[e0 + 1]);
        u64 bq23 = pack2(sB[e0 + 2],   sB[e0 + 3]);
        u64 bk01 = pack2(sB[64 + e0],     sB[64 + e0 + 1]);
        u64 bk23 = pack2(sB[64 + e0 + 2], sB[64 + e0 + 3]);
        u64 bv01 = pack2(sB[128 + e0],     sB[128 + e0 + 1]);
        u64 bv23 = pack2(sB[128 + e0 + 2], sB[128 + e0 + 3]);
        #pragma unroll
        for (int i = 0; i < 8; i++) {
            aq[i][0] = bq01; aq[i][1] = bq23;
            ak[i][0] = bk01; ak[i][1] = bk23;
            av[i][0] = bv01; av[i][1] = bv23;
        }
    }

    const float* wqp = sW + e0;
    const float* wkp = sW + 4224 + e0;
    const float* wvp = sW + 8448 + e0;
    const float* xrow = sXQ + (rg * 8) * 66;

    #pragma unroll 4
    for (int d = 0; d < 64; d += 2) {
        const float* wq0 = wqp + d * 66;
        const float* wk0 = wkp + d * 66;
        const float* wv0 = wvp + d * 66;
        u64 wq0a = *(const u64*)(wq0);      u64 wq0b = *(const u64*)(wq0 + 2);
        u64 wq1a = *(const u64*)(wq0 + 66); u64 wq1b = *(const u64*)(wq0 + 68);
        u64 wk0a = *(const u64*)(wk0);      u64 wk0b = *(const u64*)(wk0 + 2);
        u64 wk1a = *(const u64*)(wk0 + 66); u64 wk1b = *(const u64*)(wk0 + 68);
        u64 wv0a = *(const u64*)(wv0);      u64 wv0b = *(const u64*)(wv0 + 2);
        u64 wv1a = *(const u64*)(wv0 + 66); u64 wv1b = *(const u64*)(wv0 + 68);
        #pragma unroll
        for (int i = 0; i < 8; i++) {
            float2 x2 = *(const float2*)(xrow + i * 66 + d);
            u64 x0 = pack2(x2.x, x2.x);
            u64 x1 = pack2(x2.y, x2.y);
            fma2(aq[i][0], x0, wq0a); fma2(aq[i][1], x0, wq0b);
            fma2(ak[i][0], x0, wk0a); fma2(ak[i][1], x0, wk0b);
            fma2(av[i][0], x0, wv0a); fma2(av[i][1], x0, wv0b);
            fma2(aq[i][0], x1, wq1a); fma2(aq[i][1], x1, wq1b);
            fma2(ak[i][0], x1, wk1a); fma2(ak[i][1], x1, wk1b);
            fma2(av[i][0], x1, wv1a); fma2(av[i][1], x1, wv1b);
        }
    }

    __syncthreads();   // all x reads done before sXQ is overwritten with Q

    {
        float* sQ = sXQ;   // stride 65 from here on
        #pragma unroll
        for (int i = 0; i < 8; i++) {
            int row = rg * 8 + i;
            float a, b;
            unpack2(aq[i][0], a, b); sQ[row * 65 + e0]     = a; sQ[row * 65 + e0 + 1] = b;
            unpack2(aq[i][1], a, b); sQ[row * 65 + e0 + 2] = a; sQ[row * 65 + e0 + 3] = b;
            unpack2(ak[i][0], a, b); sK[row * 65 + e0]     = a; sK[row * 65 + e0 + 1] = b;
            unpack2(ak[i][1], a, b); sK[row * 65 + e0 + 2] = a; sK[row * 65 + e0 + 3] = b;
            unpack2(av[i][0], a, b); sV[row * 68 + e0]     = a; sV[row * 68 + e0 + 1] = b;
            unpack2(av[i][1], a, b); sV[row * 68 + e0 + 2] = a; sV[row * 68 + e0 + 3] = b;
        }
    }
    __syncthreads();

    // ================= Phase B: scores + exact entmax15 =================
    if (tid < 128) {
        const int t = tid >> 3;      // token in tile
        const float* sQ = sXQ;
        const float* qrow = sQ + tid * 65;
        float qreg[64];
        #pragma unroll
        for (int e = 0; e < 64; e++) qreg[e] = qrow[e];

        float s[8];
        {
            float acc[8];
            #pragma unroll
            for (int g = 0; g < 8; g++) acc[g] = 0.0f;
            const float* kb = sK + (t * 8) * 65;
            #pragma unroll 8
            for (int e = 0; e < 64; e++) {
                float qe = qreg[e];
                #pragma unroll
                for (int g = 0; g < 8; g++) acc[g] += qe * kb[g * 65 + e];
            }
            #pragma unroll
            for (int g = 0; g < 8; g++) s[g] = acc[g] * INV_SQRT_E;
        }

        // entmax15: x = (s - max)/2
        float m = s[0];
        #pragma unroll
        for (int g = 1; g < 8; g++) m = fmaxf(m, s[g]);
        float xv[8], xs[8];
        #pragma unroll
        for (int g = 0; g < 8; g++) { xv[g] = (s[g] - m) * 0.5f; xs[g] = xv[g]; }

        // Batcher odd-even mergesort, 19 comparators, descending
        #define CE(A, B) { if (xs[A] < xs[B]) { float _t = xs[A]; xs[A] = xs[B]; xs[B] = _t; } }
        CE(0,1) CE(2,3) CE(4,5) CE(6,7)
        CE(0,2) CE(1,3) CE(4,6) CE(5,7)
        CE(1,2) CE(5,6)
        CE(0,4) CE(1,5) CE(2,6) CE(3,7)
        CE(2,4) CE(3,5)
        CE(1,2) CE(3,4) CE(5,6)
        #undef CE

        // pass 1: support count (matches reference's sum(tau <= xs))
        int cnt = 0;
        {
            float cs = 0.0f, css = 0.0f;
            #pragma unroll
            for (int i = 0; i < 8; i++) {
                cs += xs[i]; css += xs[i] * xs[i];
                float rho = (float)(i + 1);
                float mean = cs / rho, msq = css / rho;
                float ss = rho * (msq - mean * mean);
                float delta = (1.0f - ss) / rho;
                float sq = (delta > 0.0f) ? sqrtf(delta) : 0.0f;
                float tau = mean - sq;
                if (tau <= xs[i]) cnt++;
            }
        }
        // pass 2: tau_star = tau[cnt-1]
        float tau_star = 0.0f;
        {
            float cs = 0.0f, css = 0.0f;
            #pragma unroll
            for (int i = 0; i < 8; i++) {
                cs += xs[i]; css += xs[i] * xs[i];
                float rho = (float)(i + 1);
                float mean = cs / rho, msq = css / rho;
                float ss = rho * (msq - mean * mean);
                float delta = (1.0f - ss) / rho;
                float sq = (delta > 0.0f) ? sqrtf(delta) : 0.0f;
                float tau = mean - sq;
                if (i == cnt - 1) tau_star = tau;
            }
        }

        float* arow = sA + tid * 9;
        #pragma unroll
        for (int g = 0; g < 8; g++) {
            float y = fmaxf(xv[g] - tau_star, 0.0f);
            arow[g] = y * y;
        }
    }
    __syncthreads();

    // ================= Phase C: out = attn @ v, coalesced float4 =================
    float* gout = out + (size_t)blk * (TB * 512);
    #pragma unroll
    for (int i = 0; i < 8; i++) {
        int idx4 = i * NTHREADS + tid;      // float4 index within tile, 0..2047
        int arowi = idx4 >> 4;               // t*8 + h
        int tt    = idx4 >> 7;               // t
        int d4    = idx4 & 15;
        const float* ar = sA + arowi * 9;
        float a[8];
        #pragma unroll
        for (int g = 0; g < 8; g++) a[g] = ar[g];
        const float* vb = sV + (tt * 8) * 68 + d4 * 4;
        float4 acc = make_float4(0.f, 0.f, 0.f, 0.f);
        #pragma unroll
        for (int g = 0; g < 8; g++) {
            float4 v4 = *(const float4*)(vb + g * 68);
            acc.x += a[g] * v4.x;
            acc.y += a[g] * v4.y;
            acc.z += a[g] * v4.z;
            acc.w += a[g] * v4.w;
        }
        *(float4*)(gout + idx4 * 4) = acc;
    }
}

extern "C" void kernel_launch(void* const* d_in, const int* in_sizes, int n_in,
                              void* d_out, int out_size) {
    const float* x  = (const float*)d_in[0];
    const float* Wq = (const float*)d_in[1];
    const float* bq = (const float*)d_in[2];
    const float* Wk = (const float*)d_in[3];
    const float* bk = (const float*)d_in[4];
    const float* Wv = (const float*)d_in[5];
    const float* bv = (const float*)d_in[6];
    float* out = (float*)d_out;

    int ntok = in_sizes[0] / 512;          // 131072
    int blocks = ntok / TB;                // 8192

    cudaFuncSetAttribute(mha_entmax_kernel,
                         cudaFuncAttributeMaxDynamicSharedMemorySize, SMEM_BYTES);
    mha_entmax_kernel<<<blocks, NTHREADS, SMEM_BYTES>>>(x, Wq, bq, Wk, bk, Wv, bv, out);
}